// round 13
// baseline (speedup 1.0000x reference)
#include <cuda_runtime.h>
#include <cuda_fp16.h>
#include <cstdint>

#define D 128
#define VCAP 100000
#define CAP 128
#define TM_ROWS 96         // rows per tensor tile (M)
#define TC_THR 384         // 12 warps: 3 row groups (32 rows) x 4 col groups (64 cols)
#define KS 136             // fp16 row stride (128 + 8 pad) -> conflict-free LDSM

// ---------------- scratch ----------------
__device__ __half g_h0[(size_t)VCAP * D];   // h0 fp16
__device__ __half g_h1[(size_t)VCAP * D];   // h1 fp16
__device__ float  g_y [(size_t)VCAP * D];
__device__ int    g_adj[(size_t)VCAP * CAP];
__device__ int    g_cnt[VCAP];
__device__ float  g_dinv[VCAP];
__device__ float  g_stats[3 * 2 * D];

// ---------------- helpers ----------------
__device__ __forceinline__ uint32_t smem_u32(const void* p) {
    return (uint32_t)__cvta_generic_to_shared(p);
}
// pack two f32 -> f16x2 (a -> lo, b -> hi)
__device__ __forceinline__ uint32_t pack_h2(float a, float b) {
    uint32_t r;
    asm("cvt.rn.f16x2.f32 %0, %1, %2;" : "=r"(r) : "f"(b), "f"(a));
    return r;
}
__device__ __forceinline__ void ldsm_x4(uint32_t addr, uint32_t r[4]) {
    asm volatile("ldmatrix.sync.aligned.m8n8.x4.shared.b16 {%0,%1,%2,%3}, [%4];"
                 : "=r"(r[0]), "=r"(r[1]), "=r"(r[2]), "=r"(r[3]) : "r"(addr));
}
__device__ __forceinline__ void mma_f16(float c[4], const uint32_t a[4],
                                        uint32_t b0, uint32_t b1) {
    asm volatile(
        "mma.sync.aligned.m16n8k16.row.col.f32.f16.f16.f32 "
        "{%0,%1,%2,%3}, {%4,%5,%6,%7}, {%8,%9}, {%0,%1,%2,%3};"
        : "+f"(c[0]), "+f"(c[1]), "+f"(c[2]), "+f"(c[3])
        : "r"(a[0]), "r"(a[1]), "r"(a[2]), "r"(a[3]), "r"(b0), "r"(b1));
}
// accumulate 8 fp16 (uint4) into float acc[8]
__device__ __forceinline__ void acc8(float acc[8], uint4 p) {
    float2 v0 = __half22float2(*(const __half2*)&p.x);
    float2 v1 = __half22float2(*(const __half2*)&p.y);
    float2 v2 = __half22float2(*(const __half2*)&p.z);
    float2 v3 = __half22float2(*(const __half2*)&p.w);
    acc[0] += v0.x; acc[1] += v0.y; acc[2] += v1.x; acc[3] += v1.y;
    acc[4] += v2.x; acc[5] += v2.y; acc[6] += v3.x; acc[7] += v3.y;
}

// ---------------- prologue kernels ----------------
__global__ void zero_kernel(int V) {
    int i = blockIdx.x * blockDim.x + threadIdx.x;
    if (i < V) g_cnt[i] = 0;
    if (i < 3 * 2 * D) g_stats[i] = 0.0f;
}

__global__ void build_adj(const int* __restrict__ edges, int E) {
    int e = blockIdx.x * blockDim.x + threadIdx.x;
    if (e >= E) return;
    int a = edges[2 * e];
    int b = edges[2 * e + 1];
    int pa = atomicAdd(&g_cnt[a], 1);
    if (pa < CAP) g_adj[(size_t)a * CAP + pa] = b;
    int pb = atomicAdd(&g_cnt[b], 1);
    if (pb < CAP) g_adj[(size_t)b * CAP + pb] = a;
}

__global__ void dinv_kernel(int V) {
    int i = blockIdx.x * blockDim.x + threadIdx.x;
    if (i < V) g_dinv[i] = 1.0f / (1.0f + (float)g_cnt[i]);
}

// ---------------- HMMA dual GEMM (fp16, 2 terms) ----------------
// h0 = f(x) @ W0^T + b0 ; h1 = f(x) @ W1^T + b1 ; both stored fp16
__global__ void __launch_bounds__(TC_THR, 1)
gemm_dual_tc(const float* __restrict__ xext, int layer,
             const float* __restrict__ W0, const float* __restrict__ b0,
             const float* __restrict__ W1, const float* __restrict__ b1,
             const float* __restrict__ gammaPrev, const float* __restrict__ betaPrev,
             int V, float invV)
{
    extern __shared__ __align__(16) char smb[];
    __half* Bhi = (__half*)smb;                       // [256][KS]
    __half* Blo = Bhi + 256 * KS;                     // [256][KS]
    __half* Ah  = Blo + 256 * KS;                     // [96][KS]

    __shared__ float s_sc[D], s_sh[D], s_bias[256];

    const float* x = (layer == 0) ? xext : g_y;
    const bool doNorm = (layer != 0);

    int tid  = threadIdx.x;
    int wid  = tid >> 5;
    int lane = tid & 31;

    if (tid < D) {
        if (doNorm) {
            const float* st = g_stats + (layer - 1) * 2 * D;
            float mu  = st[tid] * invV;
            float var = st[D + tid] * invV - mu * mu;
            float rs  = rsqrtf(var + 1e-5f);
            float sc  = gammaPrev[tid] * rs;
            s_sc[tid] = sc;
            s_sh[tid] = betaPrev[tid] - mu * sc;
        }
        s_bias[tid]     = b0[tid];
        s_bias[tid + D] = b1[tid];
    }

    // --- convert W0||W1 -> Bhi/Blo (fp16 hi + residual lo, once per block) ---
    for (int idx = tid; idx < 256 * 32; idx += TC_THR) {
        int n  = idx >> 5;
        int k4 = (idx & 31) * 4;
        const float* Wp = (n < D) ? (W0 + (size_t)n * D + k4)
                                  : (W1 + (size_t)(n - D) * D + k4);
        float4 w = *(const float4*)Wp;
        float h0 = __half2float(__float2half_rn(w.x));
        float h1 = __half2float(__float2half_rn(w.y));
        float h2 = __half2float(__float2half_rn(w.z));
        float h3 = __half2float(__float2half_rn(w.w));
        *(uint2*)(Bhi + n * KS + k4) = make_uint2(pack_h2(h0, h1), pack_h2(h2, h3));
        *(uint2*)(Blo + n * KS + k4) = make_uint2(pack_h2(w.x - h0, w.y - h1),
                                                  pack_h2(w.z - h2, w.w - h3));
    }

    // warp tiling: mw = row group (32 rows, 0..2), nw = col group (64 cols, 0..3)
    int mw = wid >> 2;
    int nw = wid & 3;
    int mrow0 = mw * 32;
    int ncolbase = nw * 64;     // within 0..255

    uint32_t aOffB = (uint32_t)(((mrow0 + (lane & 15)) * KS + (lane >> 4) * 8) * 2);
    uint32_t aAddr0 = smem_u32(Ah) + aOffB;
    uint32_t aAddr1 = aAddr0 + 16 * KS * 2;

    uint32_t bOffB = (uint32_t)(((ncolbase + (lane & 15)) * KS + (lane >> 4) * 8) * 2);
    uint32_t bHiAddr = smem_u32(Bhi) + bOffB;
    uint32_t bLoAddr = smem_u32(Blo) + bOffB;

    int ncol = (lane & 3) * 2;

    int numTiles = (V + TM_ROWS - 1) / TM_ROWS;
    int tFirst = blockIdx.x;

    // --- register prefetch of first tile ---
    float4 pf[8];
    {
        int r0 = tFirst * TM_ROWS;
        #pragma unroll
        for (int it = 0; it < 8; it++) {
            int f   = tid + it * TC_THR;
            int row = r0 + (f >> 5);
            int k4  = (f & 31) * 4;
            pf[it] = (tFirst < numTiles && row < V)
                   ? *(const float4*)(x + (size_t)row * D + k4)
                   : make_float4(0.f, 0.f, 0.f, 0.f);
        }
    }

    for (int t = tFirst; t < numTiles; t += gridDim.x) {
        int r0 = t * TM_ROWS;

        // --- convert prefetched x tile -> Ah (fused BN+ReLU for layers 1,2) ---
        #pragma unroll
        for (int it = 0; it < 8; it++) {
            int f  = tid + it * TC_THR;
            int r  = f >> 5;
            int k4 = (f & 31) * 4;
            float4 a = pf[it];
            if (doNorm) {
                a.x = fmaxf(fmaf(a.x, s_sc[k4 + 0], s_sh[k4 + 0]), 0.f);
                a.y = fmaxf(fmaf(a.y, s_sc[k4 + 1], s_sh[k4 + 1]), 0.f);
                a.z = fmaxf(fmaf(a.z, s_sc[k4 + 2], s_sh[k4 + 2]), 0.f);
                a.w = fmaxf(fmaf(a.w, s_sc[k4 + 3], s_sh[k4 + 3]), 0.f);
                if (r0 + r >= V) a = make_float4(0.f, 0.f, 0.f, 0.f);
            }
            *(uint2*)(Ah + r * KS + k4) = make_uint2(pack_h2(a.x, a.y), pack_h2(a.z, a.w));
        }
        __syncthreads();

        // --- prefetch next tile ---
        int tn = t + gridDim.x;
        if (tn < numTiles) {
            int rn0 = tn * TM_ROWS;
            #pragma unroll
            for (int it = 0; it < 8; it++) {
                int f   = tid + it * TC_THR;
                int row = rn0 + (f >> 5);
                int k4  = (f & 31) * 4;
                pf[it] = (row < V) ? *(const float4*)(x + (size_t)row * D + k4)
                                   : make_float4(0.f, 0.f, 0.f, 0.f);
            }
        }

        // --- accumulators init to bias ---
        float acc[8][8];
        #pragma unroll
        for (int n = 0; n < 8; n++) {
            float bx = s_bias[ncolbase + n * 8 + ncol];
            float by = s_bias[ncolbase + n * 8 + ncol + 1];
            acc[n][0] = bx; acc[n][1] = by; acc[n][2] = bx; acc[n][3] = by;
            acc[n][4] = bx; acc[n][5] = by; acc[n][6] = bx; acc[n][7] = by;
        }

        // --- main MMA loop: 8 k-chunks, 2 terms ---
        #pragma unroll
        for (int kc = 0; kc < 8; kc++) {
            uint32_t a0[4], a1[4];
            ldsm_x4(aAddr0 + kc * 32, a0);
            ldsm_x4(aAddr1 + kc * 32, a1);
            #pragma unroll
            for (int np = 0; np < 4; np++) {
                uint32_t bhi[4], blo[4];
                uint32_t boff = (uint32_t)(np * 16 * KS * 2 + kc * 32);
                ldsm_x4(bHiAddr + boff, bhi);
                ldsm_x4(bLoAddr + boff, blo);
                float* aE = acc[np * 2];
                float* aO = acc[np * 2 + 1];
                mma_f16(aE,     a0, bhi[0], bhi[2]);
                mma_f16(aE,     a0, blo[0], blo[2]);
                mma_f16(aO,     a0, bhi[1], bhi[3]);
                mma_f16(aO,     a0, blo[1], blo[3]);
                mma_f16(aE + 4, a1, bhi[0], bhi[2]);
                mma_f16(aE + 4, a1, blo[0], blo[2]);
                mma_f16(aO + 4, a1, bhi[1], bhi[3]);
                mma_f16(aO + 4, a1, blo[1], blo[3]);
            }
        }

        // --- epilogue: both h0 and h1 stored fp16 ---
        int rA = r0 + mrow0 + (lane >> 2);
        __half* dst = (nw < 2) ? g_h0 : g_h1;
        int cb = (nw & 1) * 64;
        #pragma unroll
        for (int n = 0; n < 8; n++) {
            int c = cb + n * 8 + ncol;
            if (rA < V)      *(uint32_t*)(dst + (size_t)rA * D + c)        = pack_h2(acc[n][0], acc[n][1]);
            if (rA + 8 < V)  *(uint32_t*)(dst + (size_t)(rA + 8) * D + c)  = pack_h2(acc[n][2], acc[n][3]);
            if (rA + 16 < V) *(uint32_t*)(dst + (size_t)(rA + 16) * D + c) = pack_h2(acc[n][4], acc[n][5]);
            if (rA + 24 < V) *(uint32_t*)(dst + (size_t)(rA + 24) * D + c) = pack_h2(acc[n][6], acc[n][7]);
        }
        __syncthreads();   // MMA readers done before next conversion overwrites A
    }
}

// ---------------- aggregation + BN stats (split-warp wide gather) ----------------
// Each warp handles one node; lanes 0-15 gather even neighbors, 16-31 odd.
// Each lane loads 16B (8 fp16 cols); cross-half reduce via shfl_xor(16).
__global__ void __launch_bounds__(256) agg_kernel(float* __restrict__ stats, int V)
{
    __shared__ float s_sum[D];
    __shared__ float s_sq[D];

    int tid  = threadIdx.x;
    int wid  = tid >> 5;
    int lane = tid & 31;
    int half = lane >> 4;      // 0 or 1
    int hl   = lane & 15;      // 0..15
    int c0   = hl * 8;         // this lane's 8 columns

    if (tid < D) { s_sum[tid] = 0.f; s_sq[tid] = 0.f; }
    __syncthreads();

    float psum[8], psq[8];
    #pragma unroll
    for (int i = 0; i < 8; i++) { psum[i] = 0.f; psq[i] = 0.f; }

    int warpStride = gridDim.x * 8;
    for (int v = blockIdx.x * 8 + wid; v < V; v += warpStride) {
        float acc[8];
        #pragma unroll
        for (int i = 0; i < 8; i++) acc[i] = 0.f;

        if (half == 0) {
            uint4 p = *(const uint4*)(g_h0 + (size_t)v * D + c0);
            acc8(acc, p);
        }

        int n = g_cnt[v];
        const int* ap = g_adj + (size_t)v * CAP;

        int e = half;
        for (; e + 2 < n; e += 4) {   // 2 loads in flight per lane
            int u0 = ap[e];
            int u1 = ap[e + 2];
            uint4 p0 = __ldg((const uint4*)(g_h1 + (size_t)u0 * D + c0));
            uint4 p1 = __ldg((const uint4*)(g_h1 + (size_t)u1 * D + c0));
            acc8(acc, p0);
            acc8(acc, p1);
        }
        if (e < n) {
            uint4 p = __ldg((const uint4*)(g_h1 + (size_t)ap[e] * D + c0));
            acc8(acc, p);
        }

        // cross-half reduce: lane hl gets half0+half1
        #pragma unroll
        for (int i = 0; i < 8; i++)
            acc[i] += __shfl_xor_sync(0xffffffffu, acc[i], 16);

        if (half == 0) {
            float dv = g_dinv[v];
            float4 o0, o1;
            o0.x = acc[0] * dv; o0.y = acc[1] * dv; o0.z = acc[2] * dv; o0.w = acc[3] * dv;
            o1.x = acc[4] * dv; o1.y = acc[5] * dv; o1.z = acc[6] * dv; o1.w = acc[7] * dv;
            *(float4*)(g_y + (size_t)v * D + c0)     = o0;
            *(float4*)(g_y + (size_t)v * D + c0 + 4) = o1;
            psum[0] += o0.x; psq[0] += o0.x * o0.x;
            psum[1] += o0.y; psq[1] += o0.y * o0.y;
            psum[2] += o0.z; psq[2] += o0.z * o0.z;
            psum[3] += o0.w; psq[3] += o0.w * o0.w;
            psum[4] += o1.x; psq[4] += o1.x * o1.x;
            psum[5] += o1.y; psq[5] += o1.y * o1.y;
            psum[6] += o1.z; psq[6] += o1.z * o1.z;
            psum[7] += o1.w; psq[7] += o1.w * o1.w;
        }
    }

    if (half == 0) {
        #pragma unroll
        for (int i = 0; i < 8; i++) {
            atomicAdd(&s_sum[c0 + i], psum[i]);
            atomicAdd(&s_sq[c0 + i],  psq[i]);
        }
    }
    __syncthreads();

    if (tid < D) {
        atomicAdd(&stats[tid],     s_sum[tid]);
        atomicAdd(&stats[D + tid], s_sq[tid]);
    }
}

// ---------------- final BN + ReLU + residual -> out ----------------
__global__ void __launch_bounds__(256) norm_final(
    const float* __restrict__ stats,
    const float* __restrict__ gamma, const float* __restrict__ beta,
    const float* __restrict__ res,
    float* __restrict__ out, int V, float invV)
{
    __shared__ float s_scale[D];
    __shared__ float s_shift[D];

    int tid = threadIdx.x;
    if (tid < D) {
        float mu  = stats[tid] * invV;
        float var = stats[D + tid] * invV - mu * mu;
        float rs  = rsqrtf(var + 1e-5f);
        float sc  = gamma[tid] * rs;
        s_scale[tid] = sc;
        s_shift[tid] = beta[tid] - mu * sc;
    }
    __syncthreads();

    int total = V * (D / 4);
    for (int f = blockIdx.x * blockDim.x + tid; f < total; f += gridDim.x * blockDim.x) {
        int c = (f & 31) * 4;
        float4 t = *(const float4*)(g_y + (size_t)f * 4);
        float4 r = *(const float4*)(res + (size_t)f * 4);
        float4 o;
        o.x = fmaxf(fmaf(t.x, s_scale[c + 0], s_shift[c + 0]) + r.x, 0.f);
        o.y = fmaxf(fmaf(t.y, s_scale[c + 1], s_shift[c + 1]) + r.y, 0.f);
        o.z = fmaxf(fmaf(t.z, s_scale[c + 2], s_shift[c + 2]) + r.z, 0.f);
        o.w = fmaxf(fmaf(t.w, s_scale[c + 3], s_shift[c + 3]) + r.w, 0.f);
        *(float4*)(out + (size_t)f * 4) = o;
    }
}

// ---------------- launch ----------------
extern "C" void kernel_launch(void* const* d_in, const int* in_sizes, int n_in,
                              void* d_out, int out_size)
{
    const float* features = (const float*)d_in[0];
    const int*   edges    = (const int*)  d_in[1];
    const float* W0       = (const float*)d_in[2];
    const float* b0       = (const float*)d_in[3];
    const float* W1       = (const float*)d_in[4];
    const float* b1       = (const float*)d_in[5];
    const float* gamma    = (const float*)d_in[6];
    const float* beta     = (const float*)d_in[7];
    float* out = (float*)d_out;

    int V = in_sizes[0] / D;
    int E = in_sizes[1] / 2;
    float invV = 1.0f / (float)V;

    // Bhi/Blo [256][KS] + Ah [96][KS], fp16
    const int SMEM_BYTES = (2 * 256 + TM_ROWS) * KS * 2;
    cudaFuncSetAttribute(gemm_dual_tc, cudaFuncAttributeMaxDynamicSharedMemorySize, SMEM_BYTES);

    float* statsP = nullptr;
    cudaGetSymbolAddress((void**)&statsP, g_stats);

    zero_kernel<<<(V + 255) / 256, 256>>>(V);
    build_adj<<<(E + 255) / 256, 256>>>(edges, E);
    dinv_kernel<<<(V + 255) / 256, 256>>>(V);

    for (int l = 0; l < 3; l++) {
        const float* gPrev = (l == 0) ? nullptr : gamma + (size_t)(l - 1) * D;
        const float* bPrev = (l == 0) ? nullptr : beta  + (size_t)(l - 1) * D;
        gemm_dual_tc<<<148, TC_THR, SMEM_BYTES>>>(
            features, l,
            W0 + (size_t)l * D * D, b0 + (size_t)l * D,
            W1 + (size_t)l * D * D, b1 + (size_t)l * D,
            gPrev, bPrev, V, invV);

        agg_kernel<<<592, 256>>>(statsP + l * 2 * D, V);
    }

    norm_final<<<1184, 256>>>(statsP + 2 * 2 * D,
                              gamma + 2 * (size_t)D, beta + 2 * (size_t)D,
                              features, out, V, invV);
}

// round 14
// speedup vs baseline: 1.0129x; 1.0129x over previous
#include <cuda_runtime.h>
#include <cuda_fp16.h>
#include <cstdint>

#define D 128
#define VCAP 100000
#define CAP 128
#define TM_ROWS 96         // rows per tensor tile (M)
#define TC_THR 384         // 12 warps: 3 row groups (32 rows) x 4 col groups (64 cols)
#define KS 136             // fp16 row stride (128 + 8 pad) -> conflict-free LDSM

// ---------------- scratch ----------------
__device__ float  g_h0[(size_t)VCAP * D];   // h0 fp32
__device__ __half g_h1[(size_t)VCAP * D];   // h1 fp16 (halves gather traffic)
__device__ float  g_y [(size_t)VCAP * D];
__device__ int    g_adj[(size_t)VCAP * CAP];
__device__ int    g_cnt[VCAP];
__device__ float  g_dinv[VCAP];
__device__ float  g_stats[3 * 2 * D];

// ---------------- helpers ----------------
__device__ __forceinline__ uint32_t smem_u32(const void* p) {
    return (uint32_t)__cvta_generic_to_shared(p);
}
// pack two f32 -> f16x2 (a -> lo, b -> hi)
__device__ __forceinline__ uint32_t pack_h2(float a, float b) {
    uint32_t r;
    asm("cvt.rn.f16x2.f32 %0, %1, %2;" : "=r"(r) : "f"(b), "f"(a));
    return r;
}
__device__ __forceinline__ void ldsm_x4(uint32_t addr, uint32_t r[4]) {
    asm volatile("ldmatrix.sync.aligned.m8n8.x4.shared.b16 {%0,%1,%2,%3}, [%4];"
                 : "=r"(r[0]), "=r"(r[1]), "=r"(r[2]), "=r"(r[3]) : "r"(addr));
}
__device__ __forceinline__ void mma_f16(float c[4], const uint32_t a[4],
                                        uint32_t b0, uint32_t b1) {
    asm volatile(
        "mma.sync.aligned.m16n8k16.row.col.f32.f16.f16.f32 "
        "{%0,%1,%2,%3}, {%4,%5,%6,%7}, {%8,%9}, {%0,%1,%2,%3};"
        : "+f"(c[0]), "+f"(c[1]), "+f"(c[2]), "+f"(c[3])
        : "r"(a[0]), "r"(a[1]), "r"(a[2]), "r"(a[3]), "r"(b0), "r"(b1));
}
// accumulate 8 fp16 (uint4) into float acc[8]
__device__ __forceinline__ void acc8(float acc[8], uint4 p) {
    float2 v0 = __half22float2(*(const __half2*)&p.x);
    float2 v1 = __half22float2(*(const __half2*)&p.y);
    float2 v2 = __half22float2(*(const __half2*)&p.z);
    float2 v3 = __half22float2(*(const __half2*)&p.w);
    acc[0] += v0.x; acc[1] += v0.y; acc[2] += v1.x; acc[3] += v1.y;
    acc[4] += v2.x; acc[5] += v2.y; acc[6] += v3.x; acc[7] += v3.y;
}

// ---------------- prologue kernels ----------------
__global__ void zero_kernel(int V) {
    int i = blockIdx.x * blockDim.x + threadIdx.x;
    if (i < V) g_cnt[i] = 0;
    if (i < 3 * 2 * D) g_stats[i] = 0.0f;
}

__global__ void build_adj(const int* __restrict__ edges, int E) {
    int e = blockIdx.x * blockDim.x + threadIdx.x;
    if (e >= E) return;
    int a = edges[2 * e];
    int b = edges[2 * e + 1];
    int pa = atomicAdd(&g_cnt[a], 1);
    if (pa < CAP) g_adj[(size_t)a * CAP + pa] = b;
    int pb = atomicAdd(&g_cnt[b], 1);
    if (pb < CAP) g_adj[(size_t)b * CAP + pb] = a;
}

__global__ void dinv_kernel(int V) {
    int i = blockIdx.x * blockDim.x + threadIdx.x;
    if (i < V) g_dinv[i] = 1.0f / (1.0f + (float)g_cnt[i]);
}

// ---------------- HMMA dual GEMM (fp16, 2 terms) — exact R12 version ----------------
// h0 = f(x) @ W0^T + b0 (fp32) ; h1 = f(x) @ W1^T + b1 (stored fp16)
__global__ void __launch_bounds__(TC_THR, 1)
gemm_dual_tc(const float* __restrict__ xext, int layer,
             const float* __restrict__ W0, const float* __restrict__ b0,
             const float* __restrict__ W1, const float* __restrict__ b1,
             const float* __restrict__ gammaPrev, const float* __restrict__ betaPrev,
             int V, float invV)
{
    extern __shared__ __align__(16) char smb[];
    __half* Bhi = (__half*)smb;                       // [256][KS]
    __half* Blo = Bhi + 256 * KS;                     // [256][KS]
    __half* Ah  = Blo + 256 * KS;                     // [96][KS]

    __shared__ float s_sc[D], s_sh[D], s_bias[256];

    const float* x = (layer == 0) ? xext : g_y;
    const bool doNorm = (layer != 0);

    int tid  = threadIdx.x;
    int wid  = tid >> 5;
    int lane = tid & 31;

    if (tid < D) {
        if (doNorm) {
            const float* st = g_stats + (layer - 1) * 2 * D;
            float mu  = st[tid] * invV;
            float var = st[D + tid] * invV - mu * mu;
            float rs  = rsqrtf(var + 1e-5f);
            float sc  = gammaPrev[tid] * rs;
            s_sc[tid] = sc;
            s_sh[tid] = betaPrev[tid] - mu * sc;
        }
        s_bias[tid]     = b0[tid];
        s_bias[tid + D] = b1[tid];
    }

    // --- convert W0||W1 -> Bhi/Blo (fp16 hi + residual lo, once per block) ---
    for (int idx = tid; idx < 256 * 32; idx += TC_THR) {
        int n  = idx >> 5;
        int k4 = (idx & 31) * 4;
        const float* Wp = (n < D) ? (W0 + (size_t)n * D + k4)
                                  : (W1 + (size_t)(n - D) * D + k4);
        float4 w = *(const float4*)Wp;
        float h0 = __half2float(__float2half_rn(w.x));
        float h1 = __half2float(__float2half_rn(w.y));
        float h2 = __half2float(__float2half_rn(w.z));
        float h3 = __half2float(__float2half_rn(w.w));
        *(uint2*)(Bhi + n * KS + k4) = make_uint2(pack_h2(h0, h1), pack_h2(h2, h3));
        *(uint2*)(Blo + n * KS + k4) = make_uint2(pack_h2(w.x - h0, w.y - h1),
                                                  pack_h2(w.z - h2, w.w - h3));
    }

    // warp tiling: mw = row group (32 rows, 0..2), nw = col group (64 cols, 0..3)
    int mw = wid >> 2;
    int nw = wid & 3;
    int mrow0 = mw * 32;
    int ncolbase = nw * 64;     // within 0..255

    uint32_t aOffB = (uint32_t)(((mrow0 + (lane & 15)) * KS + (lane >> 4) * 8) * 2);
    uint32_t aAddr0 = smem_u32(Ah) + aOffB;
    uint32_t aAddr1 = aAddr0 + 16 * KS * 2;

    uint32_t bOffB = (uint32_t)(((ncolbase + (lane & 15)) * KS + (lane >> 4) * 8) * 2);
    uint32_t bHiAddr = smem_u32(Bhi) + bOffB;
    uint32_t bLoAddr = smem_u32(Blo) + bOffB;

    int ncol = (lane & 3) * 2;

    int numTiles = (V + TM_ROWS - 1) / TM_ROWS;
    int tFirst = blockIdx.x;

    // --- register prefetch of first tile ---
    float4 pf[8];
    {
        int r0 = tFirst * TM_ROWS;
        #pragma unroll
        for (int it = 0; it < 8; it++) {
            int f   = tid + it * TC_THR;
            int row = r0 + (f >> 5);
            int k4  = (f & 31) * 4;
            pf[it] = (tFirst < numTiles && row < V)
                   ? *(const float4*)(x + (size_t)row * D + k4)
                   : make_float4(0.f, 0.f, 0.f, 0.f);
        }
    }

    for (int t = tFirst; t < numTiles; t += gridDim.x) {
        int r0 = t * TM_ROWS;

        // --- convert prefetched x tile -> Ah (fused BN+ReLU for layers 1,2) ---
        #pragma unroll
        for (int it = 0; it < 8; it++) {
            int f  = tid + it * TC_THR;
            int r  = f >> 5;
            int k4 = (f & 31) * 4;
            float4 a = pf[it];
            if (doNorm) {
                a.x = fmaxf(fmaf(a.x, s_sc[k4 + 0], s_sh[k4 + 0]), 0.f);
                a.y = fmaxf(fmaf(a.y, s_sc[k4 + 1], s_sh[k4 + 1]), 0.f);
                a.z = fmaxf(fmaf(a.z, s_sc[k4 + 2], s_sh[k4 + 2]), 0.f);
                a.w = fmaxf(fmaf(a.w, s_sc[k4 + 3], s_sh[k4 + 3]), 0.f);
                if (r0 + r >= V) a = make_float4(0.f, 0.f, 0.f, 0.f);
            }
            *(uint2*)(Ah + r * KS + k4) = make_uint2(pack_h2(a.x, a.y), pack_h2(a.z, a.w));
        }
        __syncthreads();

        // --- prefetch next tile ---
        int tn = t + gridDim.x;
        if (tn < numTiles) {
            int rn0 = tn * TM_ROWS;
            #pragma unroll
            for (int it = 0; it < 8; it++) {
                int f   = tid + it * TC_THR;
                int row = rn0 + (f >> 5);
                int k4  = (f & 31) * 4;
                pf[it] = (row < V) ? *(const float4*)(x + (size_t)row * D + k4)
                                   : make_float4(0.f, 0.f, 0.f, 0.f);
            }
        }

        // --- accumulators init to bias ---
        float acc[8][8];
        #pragma unroll
        for (int n = 0; n < 8; n++) {
            float bx = s_bias[ncolbase + n * 8 + ncol];
            float by = s_bias[ncolbase + n * 8 + ncol + 1];
            acc[n][0] = bx; acc[n][1] = by; acc[n][2] = bx; acc[n][3] = by;
            acc[n][4] = bx; acc[n][5] = by; acc[n][6] = bx; acc[n][7] = by;
        }

        // --- main MMA loop: 8 k-chunks, 2 terms ---
        #pragma unroll
        for (int kc = 0; kc < 8; kc++) {
            uint32_t a0[4], a1[4];
            ldsm_x4(aAddr0 + kc * 32, a0);
            ldsm_x4(aAddr1 + kc * 32, a1);
            #pragma unroll
            for (int np = 0; np < 4; np++) {
                uint32_t bhi[4], blo[4];
                uint32_t boff = (uint32_t)(np * 16 * KS * 2 + kc * 32);
                ldsm_x4(bHiAddr + boff, bhi);
                ldsm_x4(bLoAddr + boff, blo);
                float* aE = acc[np * 2];
                float* aO = acc[np * 2 + 1];
                mma_f16(aE,     a0, bhi[0], bhi[2]);
                mma_f16(aE,     a0, blo[0], blo[2]);
                mma_f16(aO,     a0, bhi[1], bhi[3]);
                mma_f16(aO,     a0, blo[1], blo[3]);
                mma_f16(aE + 4, a1, bhi[0], bhi[2]);
                mma_f16(aE + 4, a1, blo[0], blo[2]);
                mma_f16(aO + 4, a1, bhi[1], bhi[3]);
                mma_f16(aO + 4, a1, blo[1], blo[3]);
            }
        }

        // --- epilogue: h0 cols -> fp32 g_h0 ; h1 cols -> fp16 g_h1 ---
        int rA = r0 + mrow0 + (lane >> 2);
        int cb = (nw & 1) * 64;
        if (nw < 2) {
            #pragma unroll
            for (int n = 0; n < 8; n++) {
                int c = cb + n * 8 + ncol;
                if (rA < V)      *(float2*)(g_h0 + (size_t)rA * D + c)        = make_float2(acc[n][0], acc[n][1]);
                if (rA + 8 < V)  *(float2*)(g_h0 + (size_t)(rA + 8) * D + c)  = make_float2(acc[n][2], acc[n][3]);
                if (rA + 16 < V) *(float2*)(g_h0 + (size_t)(rA + 16) * D + c) = make_float2(acc[n][4], acc[n][5]);
                if (rA + 24 < V) *(float2*)(g_h0 + (size_t)(rA + 24) * D + c) = make_float2(acc[n][6], acc[n][7]);
            }
        } else {
            #pragma unroll
            for (int n = 0; n < 8; n++) {
                int c = cb + n * 8 + ncol;
                if (rA < V)      *(uint32_t*)(g_h1 + (size_t)rA * D + c)        = pack_h2(acc[n][0], acc[n][1]);
                if (rA + 8 < V)  *(uint32_t*)(g_h1 + (size_t)(rA + 8) * D + c)  = pack_h2(acc[n][2], acc[n][3]);
                if (rA + 16 < V) *(uint32_t*)(g_h1 + (size_t)(rA + 16) * D + c) = pack_h2(acc[n][4], acc[n][5]);
                if (rA + 24 < V) *(uint32_t*)(g_h1 + (size_t)(rA + 24) * D + c) = pack_h2(acc[n][6], acc[n][7]);
            }
        }
        __syncthreads();   // MMA readers done before next conversion overwrites A
    }
}

// ---------------- aggregation + BN stats (split-warp wide gather, h0 fp32) ----------------
// Each warp handles one node; lanes 0-15 gather even neighbors, 16-31 odd.
// Each lane loads uint4 (8 fp16 cols) per neighbor; cross-half reduce via shfl_xor(16).
__global__ void __launch_bounds__(256) agg_kernel(float* __restrict__ stats, int V)
{
    __shared__ float s_sum[D];
    __shared__ float s_sq[D];

    int tid  = threadIdx.x;
    int wid  = tid >> 5;
    int lane = tid & 31;
    int half = lane >> 4;      // 0 or 1
    int hl   = lane & 15;      // 0..15
    int c0   = hl * 8;         // this lane's 8 columns

    if (tid < D) { s_sum[tid] = 0.f; s_sq[tid] = 0.f; }
    __syncthreads();

    float psum[8], psq[8];
    #pragma unroll
    for (int i = 0; i < 8; i++) { psum[i] = 0.f; psq[i] = 0.f; }

    int warpStride = gridDim.x * 8;
    for (int v = blockIdx.x * 8 + wid; v < V; v += warpStride) {
        float acc[8];
        #pragma unroll
        for (int i = 0; i < 8; i++) acc[i] = 0.f;

        if (half == 0) {
            float4 p0 = *(const float4*)(g_h0 + (size_t)v * D + c0);
            float4 p1 = *(const float4*)(g_h0 + (size_t)v * D + c0 + 4);
            acc[0] = p0.x; acc[1] = p0.y; acc[2] = p0.z; acc[3] = p0.w;
            acc[4] = p1.x; acc[5] = p1.y; acc[6] = p1.z; acc[7] = p1.w;
        }

        int n = g_cnt[v];
        const int* ap = g_adj + (size_t)v * CAP;

        int e = half;
        for (; e + 2 < n; e += 4) {   // 2 loads in flight per lane
            int u0 = ap[e];
            int u1 = ap[e + 2];
            uint4 p0 = __ldg((const uint4*)(g_h1 + (size_t)u0 * D + c0));
            uint4 p1 = __ldg((const uint4*)(g_h1 + (size_t)u1 * D + c0));
            acc8(acc, p0);
            acc8(acc, p1);
        }
        if (e < n) {
            uint4 p = __ldg((const uint4*)(g_h1 + (size_t)ap[e] * D + c0));
            acc8(acc, p);
        }

        // cross-half reduce: half0 lane hl gets half0+half1
        #pragma unroll
        for (int i = 0; i < 8; i++)
            acc[i] += __shfl_xor_sync(0xffffffffu, acc[i], 16);

        if (half == 0) {
            float dv = g_dinv[v];
            float4 o0, o1;
            o0.x = acc[0] * dv; o0.y = acc[1] * dv; o0.z = acc[2] * dv; o0.w = acc[3] * dv;
            o1.x = acc[4] * dv; o1.y = acc[5] * dv; o1.z = acc[6] * dv; o1.w = acc[7] * dv;
            *(float4*)(g_y + (size_t)v * D + c0)     = o0;
            *(float4*)(g_y + (size_t)v * D + c0 + 4) = o1;
            psum[0] += o0.x; psq[0] += o0.x * o0.x;
            psum[1] += o0.y; psq[1] += o0.y * o0.y;
            psum[2] += o0.z; psq[2] += o0.z * o0.z;
            psum[3] += o0.w; psq[3] += o0.w * o0.w;
            psum[4] += o1.x; psq[4] += o1.x * o1.x;
            psum[5] += o1.y; psq[5] += o1.y * o1.y;
            psum[6] += o1.z; psq[6] += o1.z * o1.z;
            psum[7] += o1.w; psq[7] += o1.w * o1.w;
        }
    }

    if (half == 0) {
        #pragma unroll
        for (int i = 0; i < 8; i++) {
            atomicAdd(&s_sum[c0 + i], psum[i]);
            atomicAdd(&s_sq[c0 + i],  psq[i]);
        }
    }
    __syncthreads();

    if (tid < D) {
        atomicAdd(&stats[tid],     s_sum[tid]);
        atomicAdd(&stats[D + tid], s_sq[tid]);
    }
}

// ---------------- final BN + ReLU + residual -> out ----------------
__global__ void __launch_bounds__(256) norm_final(
    const float* __restrict__ stats,
    const float* __restrict__ gamma, const float* __restrict__ beta,
    const float* __restrict__ res,
    float* __restrict__ out, int V, float invV)
{
    __shared__ float s_scale[D];
    __shared__ float s_shift[D];

    int tid = threadIdx.x;
    if (tid < D) {
        float mu  = stats[tid] * invV;
        float var = stats[D + tid] * invV - mu * mu;
        float rs  = rsqrtf(var + 1e-5f);
        float sc  = gamma[tid] * rs;
        s_scale[tid] = sc;
        s_shift[tid] = beta[tid] - mu * sc;
    }
    __syncthreads();

    int total = V * (D / 4);
    for (int f = blockIdx.x * blockDim.x + tid; f < total; f += gridDim.x * blockDim.x) {
        int c = (f & 31) * 4;
        float4 t = *(const float4*)(g_y + (size_t)f * 4);
        float4 r = *(const float4*)(res + (size_t)f * 4);
        float4 o;
        o.x = fmaxf(fmaf(t.x, s_scale[c + 0], s_shift[c + 0]) + r.x, 0.f);
        o.y = fmaxf(fmaf(t.y, s_scale[c + 1], s_shift[c + 1]) + r.y, 0.f);
        o.z = fmaxf(fmaf(t.z, s_scale[c + 2], s_shift[c + 2]) + r.z, 0.f);
        o.w = fmaxf(fmaf(t.w, s_scale[c + 3], s_shift[c + 3]) + r.w, 0.f);
        *(float4*)(out + (size_t)f * 4) = o;
    }
}

// ---------------- launch ----------------
extern "C" void kernel_launch(void* const* d_in, const int* in_sizes, int n_in,
                              void* d_out, int out_size)
{
    const float* features = (const float*)d_in[0];
    const int*   edges    = (const int*)  d_in[1];
    const float* W0       = (const float*)d_in[2];
    const float* b0       = (const float*)d_in[3];
    const float* W1       = (const float*)d_in[4];
    const float* b1       = (const float*)d_in[5];
    const float* gamma    = (const float*)d_in[6];
    const float* beta     = (const float*)d_in[7];
    float* out = (float*)d_out;

    int V = in_sizes[0] / D;
    int E = in_sizes[1] / 2;
    float invV = 1.0f / (float)V;

    // Bhi/Blo [256][KS] + Ah [96][KS], fp16
    const int SMEM_BYTES = (2 * 256 + TM_ROWS) * KS * 2;
    cudaFuncSetAttribute(gemm_dual_tc, cudaFuncAttributeMaxDynamicSharedMemorySize, SMEM_BYTES);

    float* statsP = nullptr;
    cudaGetSymbolAddress((void**)&statsP, g_stats);

    zero_kernel<<<(V + 255) / 256, 256>>>(V);
    build_adj<<<(E + 255) / 256, 256>>>(edges, E);
    dinv_kernel<<<(V + 255) / 256, 256>>>(V);

    for (int l = 0; l < 3; l++) {
        const float* gPrev = (l == 0) ? nullptr : gamma + (size_t)(l - 1) * D;
        const float* bPrev = (l == 0) ? nullptr : beta  + (size_t)(l - 1) * D;
        gemm_dual_tc<<<148, TC_THR, SMEM_BYTES>>>(
            features, l,
            W0 + (size_t)l * D * D, b0 + (size_t)l * D,
            W1 + (size_t)l * D * D, b1 + (size_t)l * D,
            gPrev, bPrev, V, invV);

        agg_kernel<<<592, 256>>>(statsP + l * 2 * D, V);
    }

    norm_final<<<1184, 256>>>(statsP + 2 * 2 * D,
                              gamma + 2 * (size_t)D, beta + 2 * (size_t)D,
                              features, out, V, invV);
}

// round 15
// speedup vs baseline: 1.0322x; 1.0190x over previous
#include <cuda_runtime.h>
#include <cuda_fp16.h>
#include <cstdint>

#define D 128
#define VCAP 100000
#define CAP 128
#define TM_ROWS 96         // rows per tensor tile (M)
#define TC_THR 384         // 12 warps: 3 row groups (32 rows) x 4 col groups (64 cols)
#define KS 136             // fp16 row stride (128 + 8 pad) -> conflict-free LDSM

// ---------------- scratch ----------------
__device__ float  g_h0[(size_t)VCAP * D];   // h0 fp32
__device__ __half g_h1[(size_t)VCAP * D];   // h1 fp16 (halves gather traffic)
__device__ float  g_y [(size_t)VCAP * D];
__device__ int    g_adj[(size_t)VCAP * CAP];
__device__ int    g_cnt[VCAP];
__device__ float  g_stats[3 * 2 * D];

// ---------------- helpers ----------------
__device__ __forceinline__ uint32_t smem_u32(const void* p) {
    return (uint32_t)__cvta_generic_to_shared(p);
}
// pack two f32 -> f16x2 (a -> lo, b -> hi)
__device__ __forceinline__ uint32_t pack_h2(float a, float b) {
    uint32_t r;
    asm("cvt.rn.f16x2.f32 %0, %1, %2;" : "=r"(r) : "f"(b), "f"(a));
    return r;
}
__device__ __forceinline__ void ldsm_x4(uint32_t addr, uint32_t r[4]) {
    asm volatile("ldmatrix.sync.aligned.m8n8.x4.shared.b16 {%0,%1,%2,%3}, [%4];"
                 : "=r"(r[0]), "=r"(r[1]), "=r"(r[2]), "=r"(r[3]) : "r"(addr));
}
__device__ __forceinline__ void mma_f16(float c[4], const uint32_t a[4],
                                        uint32_t b0, uint32_t b1) {
    asm volatile(
        "mma.sync.aligned.m16n8k16.row.col.f32.f16.f16.f32 "
        "{%0,%1,%2,%3}, {%4,%5,%6,%7}, {%8,%9}, {%0,%1,%2,%3};"
        : "+f"(c[0]), "+f"(c[1]), "+f"(c[2]), "+f"(c[3])
        : "r"(a[0]), "r"(a[1]), "r"(a[2]), "r"(a[3]), "r"(b0), "r"(b1));
}
// accumulate 4 fp16 (uint2) into float4
__device__ __forceinline__ void acc4(float4& acc, uint2 p) {
    float2 a = __half22float2(*(const __half2*)&p.x);
    float2 b = __half22float2(*(const __half2*)&p.y);
    acc.x += a.x; acc.y += a.y; acc.z += b.x; acc.w += b.y;
}

// ---------------- prologue kernels ----------------
__global__ void zero_kernel(int V) {
    int i = blockIdx.x * blockDim.x + threadIdx.x;
    if (i < V) g_cnt[i] = 0;
    if (i < 3 * 2 * D) g_stats[i] = 0.0f;
}

__global__ void build_adj(const int* __restrict__ edges, int E) {
    int e = blockIdx.x * blockDim.x + threadIdx.x;
    if (e >= E) return;
    int a = edges[2 * e];
    int b = edges[2 * e + 1];
    int pa = atomicAdd(&g_cnt[a], 1);
    if (pa < CAP) g_adj[(size_t)a * CAP + pa] = b;
    int pb = atomicAdd(&g_cnt[b], 1);
    if (pb < CAP) g_adj[(size_t)b * CAP + pb] = a;
}

// ---------------- HMMA dual GEMM (fp16, 2 terms) — R12 version ----------------
// h0 = f(x) @ W0^T + b0 (fp32) ; h1 = f(x) @ W1^T + b1 (stored fp16)
__global__ void __launch_bounds__(TC_THR, 1)
gemm_dual_tc(const float* __restrict__ xext, int layer,
             const float* __restrict__ W0, const float* __restrict__ b0,
             const float* __restrict__ W1, const float* __restrict__ b1,
             const float* __restrict__ gammaPrev, const float* __restrict__ betaPrev,
             int V, float invV)
{
    extern __shared__ __align__(16) char smb[];
    __half* Bhi = (__half*)smb;                       // [256][KS]
    __half* Blo = Bhi + 256 * KS;                     // [256][KS]
    __half* Ah  = Blo + 256 * KS;                     // [96][KS]

    __shared__ float s_sc[D], s_sh[D], s_bias[256];

    const float* x = (layer == 0) ? xext : g_y;
    const bool doNorm = (layer != 0);

    int tid  = threadIdx.x;
    int wid  = tid >> 5;
    int lane = tid & 31;

    if (tid < D) {
        if (doNorm) {
            const float* st = g_stats + (layer - 1) * 2 * D;
            float mu  = st[tid] * invV;
            float var = st[D + tid] * invV - mu * mu;
            float rs  = rsqrtf(var + 1e-5f);
            float sc  = gammaPrev[tid] * rs;
            s_sc[tid] = sc;
            s_sh[tid] = betaPrev[tid] - mu * sc;
        }
        s_bias[tid]     = b0[tid];
        s_bias[tid + D] = b1[tid];
    }

    // --- convert W0||W1 -> Bhi/Blo (fp16 hi + residual lo, once per block) ---
    for (int idx = tid; idx < 256 * 32; idx += TC_THR) {
        int n  = idx >> 5;
        int k4 = (idx & 31) * 4;
        const float* Wp = (n < D) ? (W0 + (size_t)n * D + k4)
                                  : (W1 + (size_t)(n - D) * D + k4);
        float4 w = *(const float4*)Wp;
        float h0 = __half2float(__float2half_rn(w.x));
        float h1 = __half2float(__float2half_rn(w.y));
        float h2 = __half2float(__float2half_rn(w.z));
        float h3 = __half2float(__float2half_rn(w.w));
        *(uint2*)(Bhi + n * KS + k4) = make_uint2(pack_h2(h0, h1), pack_h2(h2, h3));
        *(uint2*)(Blo + n * KS + k4) = make_uint2(pack_h2(w.x - h0, w.y - h1),
                                                  pack_h2(w.z - h2, w.w - h3));
    }

    // warp tiling: mw = row group (32 rows, 0..2), nw = col group (64 cols, 0..3)
    int mw = wid >> 2;
    int nw = wid & 3;
    int mrow0 = mw * 32;
    int ncolbase = nw * 64;     // within 0..255

    uint32_t aOffB = (uint32_t)(((mrow0 + (lane & 15)) * KS + (lane >> 4) * 8) * 2);
    uint32_t aAddr0 = smem_u32(Ah) + aOffB;
    uint32_t aAddr1 = aAddr0 + 16 * KS * 2;

    uint32_t bOffB = (uint32_t)(((ncolbase + (lane & 15)) * KS + (lane >> 4) * 8) * 2);
    uint32_t bHiAddr = smem_u32(Bhi) + bOffB;
    uint32_t bLoAddr = smem_u32(Blo) + bOffB;

    int ncol = (lane & 3) * 2;

    int numTiles = (V + TM_ROWS - 1) / TM_ROWS;
    int tFirst = blockIdx.x;

    // --- register prefetch of first tile ---
    float4 pf[8];
    {
        int r0 = tFirst * TM_ROWS;
        #pragma unroll
        for (int it = 0; it < 8; it++) {
            int f   = tid + it * TC_THR;
            int row = r0 + (f >> 5);
            int k4  = (f & 31) * 4;
            pf[it] = (tFirst < numTiles && row < V)
                   ? *(const float4*)(x + (size_t)row * D + k4)
                   : make_float4(0.f, 0.f, 0.f, 0.f);
        }
    }

    for (int t = tFirst; t < numTiles; t += gridDim.x) {
        int r0 = t * TM_ROWS;

        // --- convert prefetched x tile -> Ah (fused BN+ReLU for layers 1,2) ---
        #pragma unroll
        for (int it = 0; it < 8; it++) {
            int f  = tid + it * TC_THR;
            int r  = f >> 5;
            int k4 = (f & 31) * 4;
            float4 a = pf[it];
            if (doNorm) {
                a.x = fmaxf(fmaf(a.x, s_sc[k4 + 0], s_sh[k4 + 0]), 0.f);
                a.y = fmaxf(fmaf(a.y, s_sc[k4 + 1], s_sh[k4 + 1]), 0.f);
                a.z = fmaxf(fmaf(a.z, s_sc[k4 + 2], s_sh[k4 + 2]), 0.f);
                a.w = fmaxf(fmaf(a.w, s_sc[k4 + 3], s_sh[k4 + 3]), 0.f);
                if (r0 + r >= V) a = make_float4(0.f, 0.f, 0.f, 0.f);
            }
            *(uint2*)(Ah + r * KS + k4) = make_uint2(pack_h2(a.x, a.y), pack_h2(a.z, a.w));
        }
        __syncthreads();

        // --- prefetch next tile ---
        int tn = t + gridDim.x;
        if (tn < numTiles) {
            int rn0 = tn * TM_ROWS;
            #pragma unroll
            for (int it = 0; it < 8; it++) {
                int f   = tid + it * TC_THR;
                int row = rn0 + (f >> 5);
                int k4  = (f & 31) * 4;
                pf[it] = (row < V) ? *(const float4*)(x + (size_t)row * D + k4)
                                   : make_float4(0.f, 0.f, 0.f, 0.f);
            }
        }

        // --- accumulators init to bias ---
        float acc[8][8];
        #pragma unroll
        for (int n = 0; n < 8; n++) {
            float bx = s_bias[ncolbase + n * 8 + ncol];
            float by = s_bias[ncolbase + n * 8 + ncol + 1];
            acc[n][0] = bx; acc[n][1] = by; acc[n][2] = bx; acc[n][3] = by;
            acc[n][4] = bx; acc[n][5] = by; acc[n][6] = bx; acc[n][7] = by;
        }

        // --- main MMA loop: 8 k-chunks, 2 terms ---
        #pragma unroll
        for (int kc = 0; kc < 8; kc++) {
            uint32_t a0[4], a1[4];
            ldsm_x4(aAddr0 + kc * 32, a0);
            ldsm_x4(aAddr1 + kc * 32, a1);
            #pragma unroll
            for (int np = 0; np < 4; np++) {
                uint32_t bhi[4], blo[4];
                uint32_t boff = (uint32_t)(np * 16 * KS * 2 + kc * 32);
                ldsm_x4(bHiAddr + boff, bhi);
                ldsm_x4(bLoAddr + boff, blo);
                float* aE = acc[np * 2];
                float* aO = acc[np * 2 + 1];
                mma_f16(aE,     a0, bhi[0], bhi[2]);
                mma_f16(aE,     a0, blo[0], blo[2]);
                mma_f16(aO,     a0, bhi[1], bhi[3]);
                mma_f16(aO,     a0, blo[1], blo[3]);
                mma_f16(aE + 4, a1, bhi[0], bhi[2]);
                mma_f16(aE + 4, a1, blo[0], blo[2]);
                mma_f16(aO + 4, a1, bhi[1], bhi[3]);
                mma_f16(aO + 4, a1, blo[1], blo[3]);
            }
        }

        // --- epilogue: h0 cols -> fp32 g_h0 ; h1 cols -> fp16 g_h1 ---
        int rA = r0 + mrow0 + (lane >> 2);
        int cb = (nw & 1) * 64;
        if (nw < 2) {
            #pragma unroll
            for (int n = 0; n < 8; n++) {
                int c = cb + n * 8 + ncol;
                if (rA < V)      *(float2*)(g_h0 + (size_t)rA * D + c)        = make_float2(acc[n][0], acc[n][1]);
                if (rA + 8 < V)  *(float2*)(g_h0 + (size_t)(rA + 8) * D + c)  = make_float2(acc[n][2], acc[n][3]);
                if (rA + 16 < V) *(float2*)(g_h0 + (size_t)(rA + 16) * D + c) = make_float2(acc[n][4], acc[n][5]);
                if (rA + 24 < V) *(float2*)(g_h0 + (size_t)(rA + 24) * D + c) = make_float2(acc[n][6], acc[n][7]);
            }
        } else {
            #pragma unroll
            for (int n = 0; n < 8; n++) {
                int c = cb + n * 8 + ncol;
                if (rA < V)      *(uint32_t*)(g_h1 + (size_t)rA * D + c)        = pack_h2(acc[n][0], acc[n][1]);
                if (rA + 8 < V)  *(uint32_t*)(g_h1 + (size_t)(rA + 8) * D + c)  = pack_h2(acc[n][2], acc[n][3]);
                if (rA + 16 < V) *(uint32_t*)(g_h1 + (size_t)(rA + 16) * D + c) = pack_h2(acc[n][4], acc[n][5]);
                if (rA + 24 < V) *(uint32_t*)(g_h1 + (size_t)(rA + 24) * D + c) = pack_h2(acc[n][6], acc[n][7]);
            }
        }
        __syncthreads();   // MMA readers done before next conversion overwrites A
    }
}

// ---------------- aggregation + BN stats (R12 structure, int4 index loads, inline dinv) ----------------
__global__ void __launch_bounds__(256) agg_kernel(float* __restrict__ stats, int V)
{
    __shared__ float s_sum[D];
    __shared__ float s_sq[D];

    int tid  = threadIdx.x;
    int wid  = tid >> 5;
    int lane = tid & 31;
    int c0   = lane * 4;

    if (tid < D) { s_sum[tid] = 0.f; s_sq[tid] = 0.f; }
    __syncthreads();

    float4 psum = make_float4(0.f, 0.f, 0.f, 0.f);
    float4 psq  = make_float4(0.f, 0.f, 0.f, 0.f);

    int warpStride = gridDim.x * 8;
    for (int v = blockIdx.x * 8 + wid; v < V; v += warpStride) {
        float4 acc = *(const float4*)(g_h0 + (size_t)v * D + c0);
        int n = g_cnt[v];
        const int* ap = g_adj + (size_t)v * CAP;
        int e = 0;
        for (; e + 3 < n; e += 4) {
            int4 u = *(const int4*)(ap + e);        // aligned: CAP row 512B-aligned, e % 4 == 0
            uint2 p0 = __ldg((const uint2*)(g_h1 + (size_t)u.x * D + c0));
            uint2 p1 = __ldg((const uint2*)(g_h1 + (size_t)u.y * D + c0));
            uint2 p2 = __ldg((const uint2*)(g_h1 + (size_t)u.z * D + c0));
            uint2 p3 = __ldg((const uint2*)(g_h1 + (size_t)u.w * D + c0));
            acc4(acc, p0); acc4(acc, p1); acc4(acc, p2); acc4(acc, p3);
        }
        for (; e < n; e++) {
            uint2 p = __ldg((const uint2*)(g_h1 + (size_t)ap[e] * D + c0));
            acc4(acc, p);
        }
        float dv = 1.0f / (1.0f + (float)n);
        acc.x *= dv; acc.y *= dv; acc.z *= dv; acc.w *= dv;
        *(float4*)(g_y + (size_t)v * D + c0) = acc;

        psum.x += acc.x; psum.y += acc.y; psum.z += acc.z; psum.w += acc.w;
        psq.x  += acc.x * acc.x; psq.y += acc.y * acc.y;
        psq.z  += acc.z * acc.z; psq.w += acc.w * acc.w;
    }

    atomicAdd(&s_sum[c0 + 0], psum.x);
    atomicAdd(&s_sum[c0 + 1], psum.y);
    atomicAdd(&s_sum[c0 + 2], psum.z);
    atomicAdd(&s_sum[c0 + 3], psum.w);
    atomicAdd(&s_sq[c0 + 0],  psq.x);
    atomicAdd(&s_sq[c0 + 1],  psq.y);
    atomicAdd(&s_sq[c0 + 2],  psq.z);
    atomicAdd(&s_sq[c0 + 3],  psq.w);
    __syncthreads();

    if (tid < D) {
        atomicAdd(&stats[tid],     s_sum[tid]);
        atomicAdd(&stats[D + tid], s_sq[tid]);
    }
}

// ---------------- final BN + ReLU + residual -> out ----------------
__global__ void __launch_bounds__(256) norm_final(
    const float* __restrict__ stats,
    const float* __restrict__ gamma, const float* __restrict__ beta,
    const float* __restrict__ res,
    float* __restrict__ out, int V, float invV)
{
    __shared__ float s_scale[D];
    __shared__ float s_shift[D];

    int tid = threadIdx.x;
    if (tid < D) {
        float mu  = stats[tid] * invV;
        float var = stats[D + tid] * invV - mu * mu;
        float rs  = rsqrtf(var + 1e-5f);
        float sc  = gamma[tid] * rs;
        s_scale[tid] = sc;
        s_shift[tid] = beta[tid] - mu * sc;
    }
    __syncthreads();

    int total = V * (D / 4);
    for (int f = blockIdx.x * blockDim.x + tid; f < total; f += gridDim.x * blockDim.x) {
        int c = (f & 31) * 4;
        float4 t = *(const float4*)(g_y + (size_t)f * 4);
        float4 r = *(const float4*)(res + (size_t)f * 4);
        float4 o;
        o.x = fmaxf(fmaf(t.x, s_scale[c + 0], s_shift[c + 0]) + r.x, 0.f);
        o.y = fmaxf(fmaf(t.y, s_scale[c + 1], s_shift[c + 1]) + r.y, 0.f);
        o.z = fmaxf(fmaf(t.z, s_scale[c + 2], s_shift[c + 2]) + r.z, 0.f);
        o.w = fmaxf(fmaf(t.w, s_scale[c + 3], s_shift[c + 3]) + r.w, 0.f);
        *(float4*)(out + (size_t)f * 4) = o;
    }
}

// ---------------- launch ----------------
extern "C" void kernel_launch(void* const* d_in, const int* in_sizes, int n_in,
                              void* d_out, int out_size)
{
    const float* features = (const float*)d_in[0];
    const int*   edges    = (const int*)  d_in[1];
    const float* W0       = (const float*)d_in[2];
    const float* b0       = (const float*)d_in[3];
    const float* W1       = (const float*)d_in[4];
    const float* b1       = (const float*)d_in[5];
    const float* gamma    = (const float*)d_in[6];
    const float* beta     = (const float*)d_in[7];
    float* out = (float*)d_out;

    int V = in_sizes[0] / D;
    int E = in_sizes[1] / 2;
    float invV = 1.0f / (float)V;

    // Bhi/Blo [256][KS] + Ah [96][KS], fp16
    const int SMEM_BYTES = (2 * 256 + TM_ROWS) * KS * 2;
    cudaFuncSetAttribute(gemm_dual_tc, cudaFuncAttributeMaxDynamicSharedMemorySize, SMEM_BYTES);

    float* statsP = nullptr;
    cudaGetSymbolAddress((void**)&statsP, g_stats);

    zero_kernel<<<(V + 255) / 256, 256>>>(V);
    build_adj<<<(E + 255) / 256, 256>>>(edges, E);

    for (int l = 0; l < 3; l++) {
        const float* gPrev = (l == 0) ? nullptr : gamma + (size_t)(l - 1) * D;
        const float* bPrev = (l == 0) ? nullptr : beta  + (size_t)(l - 1) * D;
        gemm_dual_tc<<<148, TC_THR, SMEM_BYTES>>>(
            features, l,
            W0 + (size_t)l * D * D, b0 + (size_t)l * D,
            W1 + (size_t)l * D * D, b1 + (size_t)l * D,
            gPrev, bPrev, V, invV);

        agg_kernel<<<1184, 256>>>(statsP + l * 2 * D, V);
    }

    norm_final<<<1184, 256>>>(statsP + 2 * 2 * D,
                              gamma + 2 * (size_t)D, beta + 2 * (size_t)D,
                              features, out, V, invV);
}

// round 16
// speedup vs baseline: 1.0997x; 1.0654x over previous
#include <cuda_runtime.h>
#include <cuda_fp16.h>
#include <cstdint>

#define D 128
#define VCAP 100000
#define CAP 128
#define TM_ROWS 96         // rows per tensor tile (M)
#define TC_THR 384         // 12 warps: 3 row groups (32 rows) x 4 col groups (64 cols)
#define KS 136             // fp16 row stride (128 + 8 pad) -> conflict-free LDSM

// ---------------- scratch ----------------
__device__ float  g_h0[(size_t)VCAP * D];   // h0 fp32
__device__ __half g_h1[(size_t)VCAP * D];   // h1 fp16 (halves gather traffic)
__device__ float  g_y [(size_t)VCAP * D];
__device__ int    g_adj[(size_t)VCAP * CAP];
__device__ int    g_cnt[VCAP];
__device__ float  g_stats[3 * 2 * D];

// ---------------- helpers ----------------
__device__ __forceinline__ uint32_t smem_u32(const void* p) {
    return (uint32_t)__cvta_generic_to_shared(p);
}
// pack two f32 -> f16x2 (a -> lo, b -> hi)
__device__ __forceinline__ uint32_t pack_h2(float a, float b) {
    uint32_t r;
    asm("cvt.rn.f16x2.f32 %0, %1, %2;" : "=r"(r) : "f"(b), "f"(a));
    return r;
}
__device__ __forceinline__ void ldsm_x4(uint32_t addr, uint32_t r[4]) {
    asm volatile("ldmatrix.sync.aligned.m8n8.x4.shared.b16 {%0,%1,%2,%3}, [%4];"
                 : "=r"(r[0]), "=r"(r[1]), "=r"(r[2]), "=r"(r[3]) : "r"(addr));
}
__device__ __forceinline__ void mma_f16(float c[4], const uint32_t a[4],
                                        uint32_t b0, uint32_t b1) {
    asm volatile(
        "mma.sync.aligned.m16n8k16.row.col.f32.f16.f16.f32 "
        "{%0,%1,%2,%3}, {%4,%5,%6,%7}, {%8,%9}, {%0,%1,%2,%3};"
        : "+f"(c[0]), "+f"(c[1]), "+f"(c[2]), "+f"(c[3])
        : "r"(a[0]), "r"(a[1]), "r"(a[2]), "r"(a[3]), "r"(b0), "r"(b1));
}
// accumulate 4 fp16 (uint2) into float4
__device__ __forceinline__ void acc4(float4& acc, uint2 p) {
    float2 a = __half22float2(*(const __half2*)&p.x);
    float2 b = __half22float2(*(const __half2*)&p.y);
    acc.x += a.x; acc.y += a.y; acc.z += b.x; acc.w += b.y;
}

// ---------------- prologue kernels ----------------
__global__ void zero_kernel(int V) {
    int i = blockIdx.x * blockDim.x + threadIdx.x;
    if (i < V) g_cnt[i] = 0;
    if (i < 3 * 2 * D) g_stats[i] = 0.0f;
}

__global__ void build_adj(const int* __restrict__ edges, int E) {
    int e = blockIdx.x * blockDim.x + threadIdx.x;
    if (e >= E) return;
    int a = edges[2 * e];
    int b = edges[2 * e + 1];
    int pa = atomicAdd(&g_cnt[a], 1);
    if (pa < CAP) g_adj[(size_t)a * CAP + pa] = b;
    int pb = atomicAdd(&g_cnt[b], 1);
    if (pb < CAP) g_adj[(size_t)b * CAP + pb] = a;
}

// ---------------- HMMA dual GEMM (fp16, 2 terms) — R12 version ----------------
// h0 = f(x) @ W0^T + b0 (fp32) ; h1 = f(x) @ W1^T + b1 (stored fp16)
__global__ void __launch_bounds__(TC_THR, 1)
gemm_dual_tc(const float* __restrict__ xext, int layer,
             const float* __restrict__ W0, const float* __restrict__ b0,
             const float* __restrict__ W1, const float* __restrict__ b1,
             const float* __restrict__ gammaPrev, const float* __restrict__ betaPrev,
             int V, float invV)
{
    extern __shared__ __align__(16) char smb[];
    __half* Bhi = (__half*)smb;                       // [256][KS]
    __half* Blo = Bhi + 256 * KS;                     // [256][KS]
    __half* Ah  = Blo + 256 * KS;                     // [96][KS]

    __shared__ float s_sc[D], s_sh[D], s_bias[256];

    const float* x = (layer == 0) ? xext : g_y;
    const bool doNorm = (layer != 0);

    int tid  = threadIdx.x;
    int wid  = tid >> 5;
    int lane = tid & 31;

    if (tid < D) {
        if (doNorm) {
            const float* st = g_stats + (layer - 1) * 2 * D;
            float mu  = st[tid] * invV;
            float var = st[D + tid] * invV - mu * mu;
            float rs  = rsqrtf(var + 1e-5f);
            float sc  = gammaPrev[tid] * rs;
            s_sc[tid] = sc;
            s_sh[tid] = betaPrev[tid] - mu * sc;
        }
        s_bias[tid]     = b0[tid];
        s_bias[tid + D] = b1[tid];
    }

    // --- convert W0||W1 -> Bhi/Blo (fp16 hi + residual lo, once per block) ---
    for (int idx = tid; idx < 256 * 32; idx += TC_THR) {
        int n  = idx >> 5;
        int k4 = (idx & 31) * 4;
        const float* Wp = (n < D) ? (W0 + (size_t)n * D + k4)
                                  : (W1 + (size_t)(n - D) * D + k4);
        float4 w = *(const float4*)Wp;
        float h0 = __half2float(__float2half_rn(w.x));
        float h1 = __half2float(__float2half_rn(w.y));
        float h2 = __half2float(__float2half_rn(w.z));
        float h3 = __half2float(__float2half_rn(w.w));
        *(uint2*)(Bhi + n * KS + k4) = make_uint2(pack_h2(h0, h1), pack_h2(h2, h3));
        *(uint2*)(Blo + n * KS + k4) = make_uint2(pack_h2(w.x - h0, w.y - h1),
                                                  pack_h2(w.z - h2, w.w - h3));
    }

    // warp tiling: mw = row group (32 rows, 0..2), nw = col group (64 cols, 0..3)
    int mw = wid >> 2;
    int nw = wid & 3;
    int mrow0 = mw * 32;
    int ncolbase = nw * 64;     // within 0..255

    uint32_t aOffB = (uint32_t)(((mrow0 + (lane & 15)) * KS + (lane >> 4) * 8) * 2);
    uint32_t aAddr0 = smem_u32(Ah) + aOffB;
    uint32_t aAddr1 = aAddr0 + 16 * KS * 2;

    uint32_t bOffB = (uint32_t)(((ncolbase + (lane & 15)) * KS + (lane >> 4) * 8) * 2);
    uint32_t bHiAddr = smem_u32(Bhi) + bOffB;
    uint32_t bLoAddr = smem_u32(Blo) + bOffB;

    int ncol = (lane & 3) * 2;

    int numTiles = (V + TM_ROWS - 1) / TM_ROWS;
    int tFirst = blockIdx.x;

    // --- register prefetch of first tile ---
    float4 pf[8];
    {
        int r0 = tFirst * TM_ROWS;
        #pragma unroll
        for (int it = 0; it < 8; it++) {
            int f   = tid + it * TC_THR;
            int row = r0 + (f >> 5);
            int k4  = (f & 31) * 4;
            pf[it] = (tFirst < numTiles && row < V)
                   ? *(const float4*)(x + (size_t)row * D + k4)
                   : make_float4(0.f, 0.f, 0.f, 0.f);
        }
    }

    for (int t = tFirst; t < numTiles; t += gridDim.x) {
        int r0 = t * TM_ROWS;

        // --- convert prefetched x tile -> Ah (fused BN+ReLU for layers 1,2) ---
        #pragma unroll
        for (int it = 0; it < 8; it++) {
            int f  = tid + it * TC_THR;
            int r  = f >> 5;
            int k4 = (f & 31) * 4;
            float4 a = pf[it];
            if (doNorm) {
                a.x = fmaxf(fmaf(a.x, s_sc[k4 + 0], s_sh[k4 + 0]), 0.f);
                a.y = fmaxf(fmaf(a.y, s_sc[k4 + 1], s_sh[k4 + 1]), 0.f);
                a.z = fmaxf(fmaf(a.z, s_sc[k4 + 2], s_sh[k4 + 2]), 0.f);
                a.w = fmaxf(fmaf(a.w, s_sc[k4 + 3], s_sh[k4 + 3]), 0.f);
                if (r0 + r >= V) a = make_float4(0.f, 0.f, 0.f, 0.f);
            }
            *(uint2*)(Ah + r * KS + k4) = make_uint2(pack_h2(a.x, a.y), pack_h2(a.z, a.w));
        }
        __syncthreads();

        // --- prefetch next tile ---
        int tn = t + gridDim.x;
        if (tn < numTiles) {
            int rn0 = tn * TM_ROWS;
            #pragma unroll
            for (int it = 0; it < 8; it++) {
                int f   = tid + it * TC_THR;
                int row = rn0 + (f >> 5);
                int k4  = (f & 31) * 4;
                pf[it] = (row < V) ? *(const float4*)(x + (size_t)row * D + k4)
                                   : make_float4(0.f, 0.f, 0.f, 0.f);
            }
        }

        // --- accumulators init to bias ---
        float acc[8][8];
        #pragma unroll
        for (int n = 0; n < 8; n++) {
            float bx = s_bias[ncolbase + n * 8 + ncol];
            float by = s_bias[ncolbase + n * 8 + ncol + 1];
            acc[n][0] = bx; acc[n][1] = by; acc[n][2] = bx; acc[n][3] = by;
            acc[n][4] = bx; acc[n][5] = by; acc[n][6] = bx; acc[n][7] = by;
        }

        // --- main MMA loop: 8 k-chunks, 2 terms ---
        #pragma unroll
        for (int kc = 0; kc < 8; kc++) {
            uint32_t a0[4], a1[4];
            ldsm_x4(aAddr0 + kc * 32, a0);
            ldsm_x4(aAddr1 + kc * 32, a1);
            #pragma unroll
            for (int np = 0; np < 4; np++) {
                uint32_t bhi[4], blo[4];
                uint32_t boff = (uint32_t)(np * 16 * KS * 2 + kc * 32);
                ldsm_x4(bHiAddr + boff, bhi);
                ldsm_x4(bLoAddr + boff, blo);
                float* aE = acc[np * 2];
                float* aO = acc[np * 2 + 1];
                mma_f16(aE,     a0, bhi[0], bhi[2]);
                mma_f16(aE,     a0, blo[0], blo[2]);
                mma_f16(aO,     a0, bhi[1], bhi[3]);
                mma_f16(aO,     a0, blo[1], blo[3]);
                mma_f16(aE + 4, a1, bhi[0], bhi[2]);
                mma_f16(aE + 4, a1, blo[0], blo[2]);
                mma_f16(aO + 4, a1, bhi[1], bhi[3]);
                mma_f16(aO + 4, a1, blo[1], blo[3]);
            }
        }

        // --- epilogue: h0 cols -> fp32 g_h0 ; h1 cols -> fp16 g_h1 ---
        int rA = r0 + mrow0 + (lane >> 2);
        int cb = (nw & 1) * 64;
        if (nw < 2) {
            #pragma unroll
            for (int n = 0; n < 8; n++) {
                int c = cb + n * 8 + ncol;
                if (rA < V)      *(float2*)(g_h0 + (size_t)rA * D + c)        = make_float2(acc[n][0], acc[n][1]);
                if (rA + 8 < V)  *(float2*)(g_h0 + (size_t)(rA + 8) * D + c)  = make_float2(acc[n][2], acc[n][3]);
                if (rA + 16 < V) *(float2*)(g_h0 + (size_t)(rA + 16) * D + c) = make_float2(acc[n][4], acc[n][5]);
                if (rA + 24 < V) *(float2*)(g_h0 + (size_t)(rA + 24) * D + c) = make_float2(acc[n][6], acc[n][7]);
            }
        } else {
            #pragma unroll
            for (int n = 0; n < 8; n++) {
                int c = cb + n * 8 + ncol;
                if (rA < V)      *(uint32_t*)(g_h1 + (size_t)rA * D + c)        = pack_h2(acc[n][0], acc[n][1]);
                if (rA + 8 < V)  *(uint32_t*)(g_h1 + (size_t)(rA + 8) * D + c)  = pack_h2(acc[n][2], acc[n][3]);
                if (rA + 16 < V) *(uint32_t*)(g_h1 + (size_t)(rA + 16) * D + c) = pack_h2(acc[n][4], acc[n][5]);
                if (rA + 24 < V) *(uint32_t*)(g_h1 + (size_t)(rA + 24) * D + c) = pack_h2(acc[n][6], acc[n][7]);
            }
        }
        __syncthreads();   // MMA readers done before next conversion overwrites A
    }
}

// ---------------- aggregation + BN stats (2-node pipelined gather) ----------------
__global__ void __launch_bounds__(256) agg_kernel(float* __restrict__ stats, int V)
{
    __shared__ float s_sum[D];
    __shared__ float s_sq[D];

    int tid  = threadIdx.x;
    int wid  = tid >> 5;
    int lane = tid & 31;
    int c0   = lane * 4;

    if (tid < D) { s_sum[tid] = 0.f; s_sq[tid] = 0.f; }
    __syncthreads();

    float4 psum = make_float4(0.f, 0.f, 0.f, 0.f);
    float4 psq  = make_float4(0.f, 0.f, 0.f, 0.f);

    int stride = gridDim.x * 16;     // 8 warps/block x 2 nodes/warp
    for (int v0 = blockIdx.x * 16 + wid * 2; v0 < V; v0 += stride) {
        int v1 = v0 + 1;
        bool has1 = (v1 < V);

        float4 acc0 = *(const float4*)(g_h0 + (size_t)v0 * D + c0);
        float4 acc1 = has1 ? *(const float4*)(g_h0 + (size_t)v1 * D + c0)
                           : make_float4(0.f, 0.f, 0.f, 0.f);

        int n0 = g_cnt[v0];
        int n1 = has1 ? g_cnt[v1] : 0;
        const int* ap0 = g_adj + (size_t)v0 * CAP;
        const int* ap1 = g_adj + (size_t)v1 * CAP;

        int e0 = 0, e1 = 0;
        // fused loop: both nodes' gathers in flight together
        while (e0 + 3 < n0 && e1 + 3 < n1) {
            int4 ua = *(const int4*)(ap0 + e0);
            int4 ub = *(const int4*)(ap1 + e1);
            uint2 pa0 = __ldg((const uint2*)(g_h1 + (size_t)ua.x * D + c0));
            uint2 pa1 = __ldg((const uint2*)(g_h1 + (size_t)ua.y * D + c0));
            uint2 pa2 = __ldg((const uint2*)(g_h1 + (size_t)ua.z * D + c0));
            uint2 pa3 = __ldg((const uint2*)(g_h1 + (size_t)ua.w * D + c0));
            uint2 pb0 = __ldg((const uint2*)(g_h1 + (size_t)ub.x * D + c0));
            uint2 pb1 = __ldg((const uint2*)(g_h1 + (size_t)ub.y * D + c0));
            uint2 pb2 = __ldg((const uint2*)(g_h1 + (size_t)ub.z * D + c0));
            uint2 pb3 = __ldg((const uint2*)(g_h1 + (size_t)ub.w * D + c0));
            acc4(acc0, pa0); acc4(acc0, pa1); acc4(acc0, pa2); acc4(acc0, pa3);
            acc4(acc1, pb0); acc4(acc1, pb1); acc4(acc1, pb2); acc4(acc1, pb3);
            e0 += 4; e1 += 4;
        }
        // drain node 0
        for (; e0 + 3 < n0; e0 += 4) {
            int4 u = *(const int4*)(ap0 + e0);
            uint2 p0 = __ldg((const uint2*)(g_h1 + (size_t)u.x * D + c0));
            uint2 p1 = __ldg((const uint2*)(g_h1 + (size_t)u.y * D + c0));
            uint2 p2 = __ldg((const uint2*)(g_h1 + (size_t)u.z * D + c0));
            uint2 p3 = __ldg((const uint2*)(g_h1 + (size_t)u.w * D + c0));
            acc4(acc0, p0); acc4(acc0, p1); acc4(acc0, p2); acc4(acc0, p3);
        }
        for (; e0 < n0; e0++) {
            uint2 p = __ldg((const uint2*)(g_h1 + (size_t)ap0[e0] * D + c0));
            acc4(acc0, p);
        }
        // drain node 1
        for (; e1 + 3 < n1; e1 += 4) {
            int4 u = *(const int4*)(ap1 + e1);
            uint2 p0 = __ldg((const uint2*)(g_h1 + (size_t)u.x * D + c0));
            uint2 p1 = __ldg((const uint2*)(g_h1 + (size_t)u.y * D + c0));
            uint2 p2 = __ldg((const uint2*)(g_h1 + (size_t)u.z * D + c0));
            uint2 p3 = __ldg((const uint2*)(g_h1 + (size_t)u.w * D + c0));
            acc4(acc1, p0); acc4(acc1, p1); acc4(acc1, p2); acc4(acc1, p3);
        }
        for (; e1 < n1; e1++) {
            uint2 p = __ldg((const uint2*)(g_h1 + (size_t)ap1[e1] * D + c0));
            acc4(acc1, p);
        }

        float dv0 = 1.0f / (1.0f + (float)n0);
        acc0.x *= dv0; acc0.y *= dv0; acc0.z *= dv0; acc0.w *= dv0;
        *(float4*)(g_y + (size_t)v0 * D + c0) = acc0;
        psum.x += acc0.x; psum.y += acc0.y; psum.z += acc0.z; psum.w += acc0.w;
        psq.x  += acc0.x * acc0.x; psq.y += acc0.y * acc0.y;
        psq.z  += acc0.z * acc0.z; psq.w += acc0.w * acc0.w;

        if (has1) {
            float dv1 = 1.0f / (1.0f + (float)n1);
            acc1.x *= dv1; acc1.y *= dv1; acc1.z *= dv1; acc1.w *= dv1;
            *(float4*)(g_y + (size_t)v1 * D + c0) = acc1;
            psum.x += acc1.x; psum.y += acc1.y; psum.z += acc1.z; psum.w += acc1.w;
            psq.x  += acc1.x * acc1.x; psq.y += acc1.y * acc1.y;
            psq.z  += acc1.z * acc1.z; psq.w += acc1.w * acc1.w;
        }
    }

    atomicAdd(&s_sum[c0 + 0], psum.x);
    atomicAdd(&s_sum[c0 + 1], psum.y);
    atomicAdd(&s_sum[c0 + 2], psum.z);
    atomicAdd(&s_sum[c0 + 3], psum.w);
    atomicAdd(&s_sq[c0 + 0],  psq.x);
    atomicAdd(&s_sq[c0 + 1],  psq.y);
    atomicAdd(&s_sq[c0 + 2],  psq.z);
    atomicAdd(&s_sq[c0 + 3],  psq.w);
    __syncthreads();

    if (tid < D) {
        atomicAdd(&stats[tid],     s_sum[tid]);
        atomicAdd(&stats[D + tid], s_sq[tid]);
    }
}

// ---------------- final BN + ReLU + residual -> out ----------------
__global__ void __launch_bounds__(256) norm_final(
    const float* __restrict__ stats,
    const float* __restrict__ gamma, const float* __restrict__ beta,
    const float* __restrict__ res,
    float* __restrict__ out, int V, float invV)
{
    __shared__ float s_scale[D];
    __shared__ float s_shift[D];

    int tid = threadIdx.x;
    if (tid < D) {
        float mu  = stats[tid] * invV;
        float var = stats[D + tid] * invV - mu * mu;
        float rs  = rsqrtf(var + 1e-5f);
        float sc  = gamma[tid] * rs;
        s_scale[tid] = sc;
        s_shift[tid] = beta[tid] - mu * sc;
    }
    __syncthreads();

    int total = V * (D / 4);
    for (int f = blockIdx.x * blockDim.x + tid; f < total; f += gridDim.x * blockDim.x) {
        int c = (f & 31) * 4;
        float4 t = *(const float4*)(g_y + (size_t)f * 4);
        float4 r = *(const float4*)(res + (size_t)f * 4);
        float4 o;
        o.x = fmaxf(fmaf(t.x, s_scale[c + 0], s_shift[c + 0]) + r.x, 0.f);
        o.y = fmaxf(fmaf(t.y, s_scale[c + 1], s_shift[c + 1]) + r.y, 0.f);
        o.z = fmaxf(fmaf(t.z, s_scale[c + 2], s_shift[c + 2]) + r.z, 0.f);
        o.w = fmaxf(fmaf(t.w, s_scale[c + 3], s_shift[c + 3]) + r.w, 0.f);
        *(float4*)(out + (size_t)f * 4) = o;
    }
}

// ---------------- launch ----------------
extern "C" void kernel_launch(void* const* d_in, const int* in_sizes, int n_in,
                              void* d_out, int out_size)
{
    const float* features = (const float*)d_in[0];
    const int*   edges    = (const int*)  d_in[1];
    const float* W0       = (const float*)d_in[2];
    const float* b0       = (const float*)d_in[3];
    const float* W1       = (const float*)d_in[4];
    const float* b1       = (const float*)d_in[5];
    const float* gamma    = (const float*)d_in[6];
    const float* beta     = (const float*)d_in[7];
    float* out = (float*)d_out;

    int V = in_sizes[0] / D;
    int E = in_sizes[1] / 2;
    float invV = 1.0f / (float)V;

    // Bhi/Blo [256][KS] + Ah [96][KS], fp16
    const int SMEM_BYTES = (2 * 256 + TM_ROWS) * KS * 2;
    cudaFuncSetAttribute(gemm_dual_tc, cudaFuncAttributeMaxDynamicSharedMemorySize, SMEM_BYTES);

    float* statsP = nullptr;
    cudaGetSymbolAddress((void**)&statsP, g_stats);

    zero_kernel<<<(V + 255) / 256, 256>>>(V);
    build_adj<<<(E + 255) / 256, 256>>>(edges, E);

    for (int l = 0; l < 3; l++) {
        const float* gPrev = (l == 0) ? nullptr : gamma + (size_t)(l - 1) * D;
        const float* bPrev = (l == 0) ? nullptr : beta  + (size_t)(l - 1) * D;
        gemm_dual_tc<<<148, TC_THR, SMEM_BYTES>>>(
            features, l,
            W0 + (size_t)l * D * D, b0 + (size_t)l * D,
            W1 + (size_t)l * D * D, b1 + (size_t)l * D,
            gPrev, bPrev, V, invV);

        agg_kernel<<<1184, 256>>>(statsP + l * 2 * D, V);
    }

    norm_final<<<1184, 256>>>(statsP + 2 * 2 * D,
                              gamma + 2 * (size_t)D, beta + 2 * (size_t)D,
                              features, out, V, invV);
}